// round 16
// baseline (speedup 1.0000x reference)
#include <cuda_runtime.h>
#include <cuda_bf16.h>
#include <math.h>
#include <stdint.h>

// Problem constants (fixed by the dataset)
#define NN   100000
#define EE   1600000
#define NNZ  (EE + NN)
#define C    40
#define HID  256
#define FIN  500
#define KPAD 512
#define MPAD 100096          // 782 * 128
#define LAM  0.5f
#define SCAN_NB 98           // ceil(NN/1024)

// ---------------- device scratch (no allocations allowed) ----------------
__device__ int   g_deg[NN];
__device__ float g_dinv[NN];
__device__ int   g_rowptr[NN + 1];
__device__ int   g_cursor[NN];
__device__ int   g_part[128];
__device__ __align__(128) int2  g_csr[NNZ];                    // {src, bits(weight)}
__device__ __align__(128) float g_h1[(size_t)NN * HID];        // 102 MB
__device__ __align__(128) float g_hh[(size_t)NN * C];
__device__ __align__(128) float g_xa[(size_t)NN * C];
__device__ __align__(128) float g_xb[(size_t)NN * C];
__device__ float g_score[NN];
__device__ __align__(128) __nv_bfloat16 g_whi[HID * KPAD];     // W1^T hi  [256,512]
__device__ __align__(128) __nv_bfloat16 g_wlo[HID * KPAD];     // W1^T lo

// ---------------- PTX helpers (baseline PTX only) ----------------
__device__ __forceinline__ uint32_t smem_u32(const void* p) {
    uint32_t a;
    asm("{ .reg .u64 t; cvta.to.shared.u64 t, %1; cvt.u32.u64 %0, t; }" : "=r"(a) : "l"(p));
    return a;
}
__device__ __forceinline__ void cp16(uint32_t saddr, const void* gaddr) {
    asm volatile("cp.async.cg.shared.global [%0], [%1], 16;" :: "r"(saddr), "l"(gaddr));
}
__device__ __forceinline__ void cp_commit()  { asm volatile("cp.async.commit_group;"); }
__device__ __forceinline__ void cp_wait0()   { asm volatile("cp.async.wait_group 0;"); }

__device__ __forceinline__ void ldsm4(uint32_t* r, uint32_t addr) {
    asm volatile("ldmatrix.sync.aligned.m8n8.x4.shared.b16 {%0,%1,%2,%3}, [%4];"
                 : "=r"(r[0]), "=r"(r[1]), "=r"(r[2]), "=r"(r[3]) : "r"(addr));
}
__device__ __forceinline__ void mma16816(float* d, const uint32_t* a, const uint32_t* b) {
    asm volatile(
        "mma.sync.aligned.m16n8k16.row.col.f32.bf16.bf16.f32 "
        "{%0,%1,%2,%3}, {%4,%5,%6,%7}, {%8,%9}, {%0,%1,%2,%3};"
        : "+f"(d[0]), "+f"(d[1]), "+f"(d[2]), "+f"(d[3])
        : "r"(a[0]), "r"(a[1]), "r"(a[2]), "r"(a[3]), "r"(b[0]), "r"(b[1]));
}
__device__ __forceinline__ void lds128f(float4& v, uint32_t a) {
    asm volatile("ld.shared.v4.f32 {%0,%1,%2,%3}, [%4];"
                 : "=f"(v.x), "=f"(v.y), "=f"(v.z), "=f"(v.w) : "r"(a));
}
__device__ __forceinline__ void sts64_2(uint32_t a, uint32_t u0, uint32_t u1) {
    asm volatile("st.shared.v2.b32 [%0], {%1, %2};" :: "r"(a), "r"(u0), "r"(u1) : "memory");
}
__device__ __forceinline__ void sts_zero16(uint32_t a) {
    asm volatile("st.shared.v4.b32 [%0], {%1,%1,%1,%1};" :: "r"(a), "r"(0) : "memory");
}

// ---------------- W split conversion (tiny, stays a kernel) ----------------
__global__ __launch_bounds__(256) void k_convW(const float* __restrict__ W1) {
    int idx = blockIdx.x * 256 + threadIdx.x;
    if (idx >= HID * KPAD) return;
    int n = idx >> 9, k = idx & 511;
    float v = (k < FIN) ? W1[(size_t)k * HID + n] : 0.f;   // transpose
    __nv_bfloat16 hi = __float2bfloat16_rn(v);
    __nv_bfloat16 lo = __float2bfloat16_rn(v - __bfloat162float(hi));
    g_whi[idx] = hi;
    g_wlo[idx] = lo;
}

// ---------------- GEMM1 via mma.sync bf16 (2-term split, FUSED x-conversion) ----------------
// CTA tile 128m x 128n, K chunks of 32. A loaded as fp32 from x into a single
// 16KB smem staging buffer; per-chunk convert phase splits to hi/lo bf16 tiles.
// 8 warps (4m x 2n), warp tile 32x64. 3 products: hi*hi + hi*lo + lo*hi.
#define ROWB   80                      // bf16 tile row stride (64B data + 16B pad)
#define T_AHI  0
#define T_ALO  10240
#define T_BHI  20480
#define T_BLO  30720
#define STAGE  40960
#define SM_AF32   0                    // fp32 A staging: 128 rows * 128B = 16384
#define SM_TILES  16384
#define SM_G1  (SM_TILES + 2 * STAGE)  // 98304 bytes -> 2 CTAs/SM

__device__ __forceinline__ void fill_B(uint32_t ss, int c, int bn, int t) {
#pragma unroll
    for (int i = 0; i < 2; ++i) {
        int seg = t + i * 256;         // 0..511
        int r = seg >> 2, s4 = seg & 3;
        uint32_t so = (uint32_t)(r * ROWB + s4 * 16);
        size_t gb = (size_t)(bn * 128 + r) * KPAD + c * 32 + s4 * 8;
        cp16(ss + T_BHI + so, g_whi + gb);
        cp16(ss + T_BLO + so, g_wlo + gb);
    }
}

__device__ __forceinline__ void fill_Af32(uint32_t sA, const float* __restrict__ x,
                                          int c, int bm, int t) {
#pragma unroll
    for (int i = 0; i < 4; ++i) {
        int seg = t + i * 256;         // 0..1023
        int r = seg >> 3, f4 = seg & 7;
        int col = c * 32 + f4 * 4;
        int row = bm + r;
        uint32_t so = (uint32_t)(r * 128 + f4 * 16);
        if (row < NN && col < FIN)     // FIN%4==0 -> whole-float4 predication exact
            cp16(sA + so, x + (size_t)row * FIN + col);
        else
            sts_zero16(sA + so);
    }
}

__device__ __forceinline__ void convertA(uint32_t sA, uint32_t st, int t) {
#pragma unroll
    for (int i = 0; i < 4; ++i) {
        int seg = t + i * 256;
        int r = seg >> 3, f4 = seg & 7;
        float4 v;
        lds128f(v, sA + (uint32_t)(r * 128 + f4 * 16));
        __nv_bfloat16 h0 = __float2bfloat16_rn(v.x);
        __nv_bfloat16 h1 = __float2bfloat16_rn(v.y);
        __nv_bfloat16 h2 = __float2bfloat16_rn(v.z);
        __nv_bfloat16 h3 = __float2bfloat16_rn(v.w);
        __nv_bfloat16 l0 = __float2bfloat16_rn(v.x - __bfloat162float(h0));
        __nv_bfloat16 l1 = __float2bfloat16_rn(v.y - __bfloat162float(h1));
        __nv_bfloat16 l2 = __float2bfloat16_rn(v.z - __bfloat162float(h2));
        __nv_bfloat16 l3 = __float2bfloat16_rn(v.w - __bfloat162float(h3));
        uint32_t h01 = ((uint32_t)__bfloat16_as_ushort(h1) << 16) | __bfloat16_as_ushort(h0);
        uint32_t h23 = ((uint32_t)__bfloat16_as_ushort(h3) << 16) | __bfloat16_as_ushort(h2);
        uint32_t l01 = ((uint32_t)__bfloat16_as_ushort(l1) << 16) | __bfloat16_as_ushort(l0);
        uint32_t l23 = ((uint32_t)__bfloat16_as_ushort(l3) << 16) | __bfloat16_as_ushort(l2);
        uint32_t ro = (uint32_t)(r * ROWB + f4 * 8);
        sts64_2(st + T_AHI + ro, h01, h23);
        sts64_2(st + T_ALO + ro, l01, l23);
    }
}

__global__ __launch_bounds__(256, 2) void k_gemm1_mma(const float* __restrict__ x,
                                                      const float* __restrict__ b1) {
    extern __shared__ char smem[];
    uint32_t sb = smem_u32(smem);
    uint32_t sA = sb + SM_AF32;
    uint32_t stiles = sb + SM_TILES;
    int t = threadIdx.x, wid = t >> 5, lane = t & 31;
    int wm = wid >> 1, wn = wid & 1;           // 4 x 2 warp grid
    int bn = blockIdx.x, bm = blockIdx.y * 128;
    int r8 = lane & 7, mi = lane >> 3;

    float acc[2][8][4];
#pragma unroll
    for (int a = 0; a < 2; ++a)
#pragma unroll
        for (int b = 0; b < 8; ++b)
#pragma unroll
            for (int q = 0; q < 4; ++q) acc[a][b][q] = 0.f;

    fill_Af32(sA, x, 0, bm, t);
    fill_B(stiles, 0, bn, t);
    cp_commit();

    for (int c = 0; c < 16; ++c) {
        cp_wait0();                      // A(c) staging + B(c) tiles resident
        __syncthreads();                 // also: prior compute's reads complete
        uint32_t st = stiles + (uint32_t)(c & 1) * STAGE;
        convertA(sA, st, t);             // fp32 staging -> hi/lo bf16 tiles
        __syncthreads();                 // tiles visible; staging free
        if (c < 15) {
            fill_Af32(sA, x, c + 1, bm, t);
            fill_B(stiles + (uint32_t)((c + 1) & 1) * STAGE, c + 1, bn, t);
            cp_commit();                 // overlaps with compute below
        }

#pragma unroll
        for (int ks = 0; ks < 2; ++ks) {
            uint32_t ahi[2][4], alo[2][4];
#pragma unroll
            for (int mt = 0; mt < 2; ++mt) {
                uint32_t ao = (uint32_t)((wm * 32 + mt * 16 + (mi & 1) * 8 + r8) * ROWB
                                         + (ks * 16 + (mi >> 1) * 8) * 2);
                ldsm4(ahi[mt], st + T_AHI + ao);
                ldsm4(alo[mt], st + T_ALO + ao);
            }
            uint32_t bhi[4][4], blo[4][4];
#pragma unroll
            for (int ng = 0; ng < 4; ++ng) {
                uint32_t bo = (uint32_t)((wn * 64 + ng * 16 + (mi >> 1) * 8 + r8) * ROWB
                                         + (ks * 16 + (mi & 1) * 8) * 2);
                ldsm4(bhi[ng], st + T_BHI + bo);
                ldsm4(blo[ng], st + T_BLO + bo);
            }
#pragma unroll
            for (int mt = 0; mt < 2; ++mt)
#pragma unroll
                for (int nt = 0; nt < 8; ++nt) {
                    const uint32_t* bh = &bhi[nt >> 1][(nt & 1) * 2];
                    const uint32_t* bl = &blo[nt >> 1][(nt & 1) * 2];
                    mma16816(acc[mt][nt], ahi[mt], bh);
                    mma16816(acc[mt][nt], ahi[mt], bl);
                    mma16816(acc[mt][nt], alo[mt], bh);
                }
        }
    }

    // epilogue: bias + relu
    int qr = lane >> 2, qc = (lane & 3) * 2;
#pragma unroll
    for (int nt = 0; nt < 8; ++nt) {
        int col = bn * 128 + wn * 64 + nt * 8 + qc;
        float bv0 = b1[col], bv1 = b1[col + 1];
#pragma unroll
        for (int mt = 0; mt < 2; ++mt) {
            int row0 = bm + wm * 32 + mt * 16 + qr;
            if (row0 < NN) {
                float2 v;
                v.x = fmaxf(acc[mt][nt][0] + bv0, 0.f);
                v.y = fmaxf(acc[mt][nt][1] + bv1, 0.f);
                *(float2*)(g_h1 + (size_t)row0 * HID + col) = v;
            }
            if (row0 + 8 < NN) {
                float2 v;
                v.x = fmaxf(acc[mt][nt][2] + bv0, 0.f);
                v.y = fmaxf(acc[mt][nt][3] + bv1, 0.f);
                *(float2*)(g_h1 + (size_t)(row0 + 8) * HID + col) = v;
            }
        }
    }
}

// ---------------- graph normalization + CSR build ----------------
__global__ void k_init() {
    int i = blockIdx.x * blockDim.x + threadIdx.x;
    if (i < NN) g_deg[i] = 1;
}
__global__ void k_count(const int* __restrict__ dst, int E) {
    int e = blockIdx.x * blockDim.x + threadIdx.x;
    if (e < E) atomicAdd(&g_deg[dst[e]], 1);
}
__global__ void k_dinv() {
    int i = blockIdx.x * blockDim.x + threadIdx.x;
    if (i < NN) g_dinv[i] = rsqrtf((float)g_deg[i]);
}
__global__ void k_scanA() {
    __shared__ int sh[256];
    int b = blockIdx.x, t = threadIdx.x;
    int base = b * 1024 + t * 4;
    int s = 0;
    if (base < NN) { int4 v = *(const int4*)(g_deg + base); s = v.x + v.y + v.z + v.w; }
    sh[t] = s; __syncthreads();
    for (int off = 128; off > 0; off >>= 1) {
        if (t < off) sh[t] += sh[t + off];
        __syncthreads();
    }
    if (t == 0) g_part[b] = sh[0];
}
__global__ void k_scanB(int nnz_total) {
    __shared__ int sh[128];
    int t = threadIdx.x;
    int v = (t < SCAN_NB) ? g_part[t] : 0;
    sh[t] = v; __syncthreads();
    for (int off = 1; off < 128; off <<= 1) {
        int u = (t >= off) ? sh[t - off] : 0;
        __syncthreads();
        sh[t] += u;
        __syncthreads();
    }
    g_part[t] = sh[t] - v;
    if (t == 0) g_rowptr[NN] = nnz_total;
}
__global__ void k_scanC() {
    __shared__ int sh[256];
    int b = blockIdx.x, t = threadIdx.x;
    int base = b * 1024 + t * 4;
    int4 v = make_int4(0, 0, 0, 0);
    if (base < NN) v = *(const int4*)(g_deg + base);
    int s1 = v.x, s2 = s1 + v.y, s3 = s2 + v.z, tot = s3 + v.w;
    sh[t] = tot; __syncthreads();
    for (int off = 1; off < 256; off <<= 1) {
        int u = (t >= off) ? sh[t - off] : 0;
        __syncthreads();
        sh[t] += u;
        __syncthreads();
    }
    int o = g_part[b] + sh[t] - tot;
    if (base < NN)
        *(int4*)(g_rowptr + base) = make_int4(o, o + s1, o + s2, o + s3);
}
__global__ void k_fill_self() {
    int i = blockIdx.x * blockDim.x + threadIdx.x;
    if (i >= NN) return;
    int p = g_rowptr[i];
    float di = g_dinv[i];
    g_csr[p] = make_int2(i, __float_as_int(di * di));
    g_cursor[i] = p + 1;
}
__global__ void k_fill_edges(const int* __restrict__ src, const int* __restrict__ dst, int E) {
    int e = blockIdx.x * blockDim.x + threadIdx.x;
    if (e >= E) return;
    int s = src[e], d = dst[e];
    int p = atomicAdd(&g_cursor[d], 1);
    g_csr[p] = make_int2(s, __float_as_int(g_dinv[s] * g_dinv[d]));
}

// ---------------- GEMM2: hh = h1 @ W2 + b2 ----------------
__global__ __launch_bounds__(256) void k_gemm2(const float* __restrict__ W2,
                                               const float* __restrict__ b2) {
    __shared__ float sW[HID * C];
    int t = threadIdx.x;
    for (int i = t; i < HID * C; i += 256) sW[i] = W2[i];
    __syncthreads();
    int row = blockIdx.x * 8 + (t >> 5);
    int lane = t & 31;
    if (row >= NN) return;
    const float4* h4 = (const float4*)(g_h1 + (size_t)row * HID);
    float a0 = 0.f, a1 = 0.f;
    int c1 = 32 + lane;
#pragma unroll 4
    for (int k4 = 0; k4 < HID / 4; k4++) {
        float4 h = h4[k4];
        int kb = k4 * 4;
        a0 = fmaf(h.x, sW[(kb + 0) * C + lane], a0);
        a0 = fmaf(h.y, sW[(kb + 1) * C + lane], a0);
        a0 = fmaf(h.z, sW[(kb + 2) * C + lane], a0);
        a0 = fmaf(h.w, sW[(kb + 3) * C + lane], a0);
        if (lane < 8) {
            a1 = fmaf(h.x, sW[(kb + 0) * C + c1], a1);
            a1 = fmaf(h.y, sW[(kb + 1) * C + c1], a1);
            a1 = fmaf(h.z, sW[(kb + 2) * C + c1], a1);
            a1 = fmaf(h.w, sW[(kb + 3) * C + c1], a1);
        }
    }
    float* o = g_hh + (size_t)row * C;
    o[lane] = a0 + b2[lane];
    if (lane < 8) o[c1] = a1 + b2[c1];
}

// ---------------- fused SpMM + L21 proximal (float4 gather, 10 active lanes) ----------------
// Per edge: 1 LDG.64 (csr, broadcast) + 1 LDG.128 (row gather) = 2 LDG issues
// (was 3). Row base 160*i bytes is 16B-aligned; lanes 0-9 cover all 40 floats.
__global__ __launch_bounds__(256) void k_amp(int it) {
    const float* __restrict__ xin = (it == 0) ? g_hh : ((it & 1) ? g_xa : g_xb);
    float* __restrict__ xout = (it & 1) ? g_xb : g_xa;
    int gid = blockIdx.x * blockDim.x + threadIdx.x;
    int i = gid >> 5, lane = gid & 31;
    if (i >= NN) return;
    int rs = g_rowptr[i], re = g_rowptr[i + 1];
    bool act = lane < 10;
    size_t lo = (size_t)lane * 4;
    float4 acc = make_float4(0.f, 0.f, 0.f, 0.f);
    for (int e = rs; e < re; ++e) {
        int2 cv = g_csr[e];
        float w = __int_as_float(cv.y);
        if (act) {
            float4 xv = *(const float4*)(xin + (size_t)cv.x * C + lo);
            acc.x = fmaf(w, xv.x, acc.x);
            acc.y = fmaf(w, xv.y, acc.y);
            acc.z = fmaf(w, xv.z, acc.z);
            acc.w = fmaf(w, xv.w, acc.w);
        }
    }
    float4 h = make_float4(0.f, 0.f, 0.f, 0.f);
    if (act) h = *(const float4*)(g_hh + (size_t)i * C + lo);
    float4 d;
    d.x = acc.x - h.x; d.y = acc.y - h.y; d.z = acc.z - h.z; d.w = acc.w - h.w;
    float p = act ? (d.x * d.x + d.y * d.y + d.z * d.z + d.w * d.w) : 0.f;
#pragma unroll
    for (int off = 16; off > 0; off >>= 1) p += __shfl_xor_sync(0xffffffffu, p, off);
    float rn = sqrtf(p);
    float sc = 0.f;
    if (rn > 0.f) sc = fmaxf(rn - LAM, 0.f) / rn;
    if (act) {
        float4 o;
        o.x = h.x + sc * d.x; o.y = h.y + sc * d.y;
        o.z = h.z + sc * d.z; o.w = h.w + sc * d.w;
        *(float4*)(xout + (size_t)i * C + lo) = o;
    }
    if (lane == 0) g_score[i] = sc;
}

// ---------------- log_softmax + output assembly ----------------
__global__ __launch_bounds__(256) void k_out(float* __restrict__ out) {
    int gid = blockIdx.x * blockDim.x + threadIdx.x;
    int i = gid >> 5, lane = gid & 31;
    if (i >= NN) return;
    const float* xr = g_xb + (size_t)i * C;
    float v0 = xr[lane];
    float v1 = (lane < 8) ? xr[32 + lane] : 0.f;
    float m = (lane < 8) ? fmaxf(v0, v1) : v0;
#pragma unroll
    for (int off = 16; off > 0; off >>= 1) m = fmaxf(m, __shfl_xor_sync(0xffffffffu, m, off));
    float s = expf(v0 - m) + ((lane < 8) ? expf(v1 - m) : 0.f);
#pragma unroll
    for (int off = 16; off > 0; off >>= 1) s += __shfl_xor_sync(0xffffffffu, s, off);
    float l = logf(s);
    out[(size_t)i * C + lane] = v0 - m - l;
    if (lane < 8) out[(size_t)i * C + 32 + lane] = v1 - m - l;
    if (lane == 0) out[(size_t)NN * C + i] = g_score[i];
}

// ---------------- launch ----------------
extern "C" void kernel_launch(void* const* d_in, const int* in_sizes, int n_in,
                              void* d_out, int out_size) {
    const float* x   = (const float*)d_in[0];
    const float* W1  = (const float*)d_in[1];
    const float* b1  = (const float*)d_in[2];
    const float* W2  = (const float*)d_in[3];
    const float* b2  = (const float*)d_in[4];
    const int* esrc  = (const int*)d_in[5];
    const int* edst  = (const int*)d_in[6];
    int E = in_sizes[5];
    if (E > EE) E = EE;
    float* out = (float*)d_out;

    cudaFuncSetAttribute(k_gemm1_mma, cudaFuncAttributeMaxDynamicSharedMemorySize, SM_G1);

    // order keeps gemm1 at launch index 3 (= ncu capture slot)
    k_convW<<<(HID * KPAD + 255) / 256, 256>>>(W1);             // 0
    k_init<<<(NN + 255) / 256, 256>>>();                        // 1
    k_count<<<(E + 255) / 256, 256>>>(edst, E);                 // 2
    {
        dim3 g1(2, MPAD / 128);
        k_gemm1_mma<<<g1, 256, SM_G1>>>(x, b1);                 // 3  (ncu slot)
    }

    // graph normalization + CSR build
    k_dinv<<<(NN + 255) / 256, 256>>>();
    k_scanA<<<SCAN_NB, 256>>>();
    k_scanB<<<1, 128>>>(E + NN);
    k_scanC<<<SCAN_NB, 256>>>();
    k_fill_self<<<(NN + 255) / 256, 256>>>();
    k_fill_edges<<<(E + 255) / 256, 256>>>(esrc, edst, E);

    // MLP second layer
    k_gemm2<<<(NN + 7) / 8, 256>>>(W2, b2);

    // 10 AMP iterations (ping-pong)
    int warpBlocks = (NN * 32 + 255) / 256;
    for (int it = 0; it < 10; ++it)
        k_amp<<<warpBlocks, 256>>>(it);

    // log_softmax + score
    k_out<<<warpBlocks, 256>>>(out);
}

// round 17
// speedup vs baseline: 1.0415x; 1.0415x over previous
#include <cuda_runtime.h>
#include <cuda_bf16.h>
#include <math.h>
#include <stdint.h>

// Problem constants (fixed by the dataset)
#define NN   100000
#define EE   1600000
#define NNZ  (EE + NN)
#define C    40
#define HID  256
#define FIN  500
#define KPAD 512
#define MPAD 100096          // 782 * 128
#define LAM  0.5f
#define SCAN_NB 98           // ceil(NN/1024)

// ---------------- device scratch (no allocations allowed) ----------------
__device__ int   g_deg[NN];
__device__ float g_dinv[NN];
__device__ int   g_rowptr[NN + 1];
__device__ int   g_cursor[NN];
__device__ int   g_part[128];
__device__ __align__(128) int2  g_csr[NNZ];                    // {src, bits(weight)}
__device__ __align__(128) float g_h1[(size_t)NN * HID];        // 102 MB
__device__ __align__(128) float g_hh[(size_t)NN * C];
__device__ __align__(128) float g_xa[(size_t)NN * C];
__device__ __align__(128) float g_xb[(size_t)NN * C];
__device__ float g_score[NN];
__device__ __align__(128) __nv_bfloat16 g_whi[HID * KPAD];     // W1^T hi  [256,512]
__device__ __align__(128) __nv_bfloat16 g_wlo[HID * KPAD];     // W1^T lo

// ---------------- PTX helpers (baseline PTX only) ----------------
__device__ __forceinline__ uint32_t smem_u32(const void* p) {
    uint32_t a;
    asm("{ .reg .u64 t; cvta.to.shared.u64 t, %1; cvt.u32.u64 %0, t; }" : "=r"(a) : "l"(p));
    return a;
}
__device__ __forceinline__ void cp16(uint32_t saddr, const void* gaddr) {
    asm volatile("cp.async.cg.shared.global [%0], [%1], 16;" :: "r"(saddr), "l"(gaddr));
}
__device__ __forceinline__ void cp_commit()  { asm volatile("cp.async.commit_group;"); }
__device__ __forceinline__ void cp_wait0()   { asm volatile("cp.async.wait_group 0;"); }

__device__ __forceinline__ void ldsm4(uint32_t* r, uint32_t addr) {
    asm volatile("ldmatrix.sync.aligned.m8n8.x4.shared.b16 {%0,%1,%2,%3}, [%4];"
                 : "=r"(r[0]), "=r"(r[1]), "=r"(r[2]), "=r"(r[3]) : "r"(addr));
}
__device__ __forceinline__ void mma16816(float* d, const uint32_t* a, const uint32_t* b) {
    asm volatile(
        "mma.sync.aligned.m16n8k16.row.col.f32.bf16.bf16.f32 "
        "{%0,%1,%2,%3}, {%4,%5,%6,%7}, {%8,%9}, {%0,%1,%2,%3};"
        : "+f"(d[0]), "+f"(d[1]), "+f"(d[2]), "+f"(d[3])
        : "r"(a[0]), "r"(a[1]), "r"(a[2]), "r"(a[3]), "r"(b[0]), "r"(b[1]));
}
__device__ __forceinline__ void lds128f(float4& v, uint32_t a) {
    asm volatile("ld.shared.v4.f32 {%0,%1,%2,%3}, [%4];"
                 : "=f"(v.x), "=f"(v.y), "=f"(v.z), "=f"(v.w) : "r"(a));
}
__device__ __forceinline__ void sts64_2(uint32_t a, uint32_t u0, uint32_t u1) {
    asm volatile("st.shared.v2.b32 [%0], {%1, %2};" :: "r"(a), "r"(u0), "r"(u1) : "memory");
}
__device__ __forceinline__ void sts_zero16(uint32_t a) {
    asm volatile("st.shared.v4.b32 [%0], {%1,%1,%1,%1};" :: "r"(a), "r"(0) : "memory");
}

// ---------------- W split conversion (tiny, stays a kernel) ----------------
__global__ __launch_bounds__(256) void k_convW(const float* __restrict__ W1) {
    int idx = blockIdx.x * 256 + threadIdx.x;
    if (idx >= HID * KPAD) return;
    int n = idx >> 9, k = idx & 511;
    float v = (k < FIN) ? W1[(size_t)k * HID + n] : 0.f;   // transpose
    __nv_bfloat16 hi = __float2bfloat16_rn(v);
    __nv_bfloat16 lo = __float2bfloat16_rn(v - __bfloat162float(hi));
    g_whi[idx] = hi;
    g_wlo[idx] = lo;
}

// ---------------- GEMM1 via mma.sync bf16 (2-term split, FUSED x-conversion) ----------------
// CTA tile 128m x 128n, K chunks of 32. A loaded as fp32 from x into a DOUBLE-
// BUFFERED 16KB smem staging buffer; per-chunk convert splits to hi/lo bf16
// tiles. Next-chunk fills (A staging + B tiles) are issued BEFORE convertA so
// cp.async overlaps convert+mma. 8 warps (4m x 2n), warp tile 32x64.
// 3 products: hi*hi + hi*lo + lo*hi.
#define ROWB   80                      // bf16 tile row stride (64B data + 16B pad)
#define T_AHI  0
#define T_ALO  10240
#define T_BHI  20480
#define T_BLO  30720
#define STAGE  40960
#define SM_AF32   0                    // fp32 A staging: 2 x (128 rows * 128B) = 32768
#define AF32_SZ   16384
#define SM_TILES  32768
#define SM_G1  (SM_TILES + 2 * STAGE)  // 114688 bytes -> still 2 CTAs/SM (2*(114688+1024) <= 233472)

__device__ __forceinline__ void fill_B(uint32_t ss, int c, int bn, int t) {
#pragma unroll
    for (int i = 0; i < 2; ++i) {
        int seg = t + i * 256;         // 0..511
        int r = seg >> 2, s4 = seg & 3;
        uint32_t so = (uint32_t)(r * ROWB + s4 * 16);
        size_t gb = (size_t)(bn * 128 + r) * KPAD + c * 32 + s4 * 8;
        cp16(ss + T_BHI + so, g_whi + gb);
        cp16(ss + T_BLO + so, g_wlo + gb);
    }
}

__device__ __forceinline__ void fill_Af32(uint32_t sA, const float* __restrict__ x,
                                          int c, int bm, int t) {
#pragma unroll
    for (int i = 0; i < 4; ++i) {
        int seg = t + i * 256;         // 0..1023
        int r = seg >> 3, f4 = seg & 7;
        int col = c * 32 + f4 * 4;
        int row = bm + r;
        uint32_t so = (uint32_t)(r * 128 + f4 * 16);
        if (row < NN && col < FIN)     // FIN%4==0 -> whole-float4 predication exact
            cp16(sA + so, x + (size_t)row * FIN + col);
        else
            sts_zero16(sA + so);
    }
}

__device__ __forceinline__ void convertA(uint32_t sA, uint32_t st, int t) {
#pragma unroll
    for (int i = 0; i < 4; ++i) {
        int seg = t + i * 256;
        int r = seg >> 3, f4 = seg & 7;
        float4 v;
        lds128f(v, sA + (uint32_t)(r * 128 + f4 * 16));
        __nv_bfloat16 h0 = __float2bfloat16_rn(v.x);
        __nv_bfloat16 h1 = __float2bfloat16_rn(v.y);
        __nv_bfloat16 h2 = __float2bfloat16_rn(v.z);
        __nv_bfloat16 h3 = __float2bfloat16_rn(v.w);
        __nv_bfloat16 l0 = __float2bfloat16_rn(v.x - __bfloat162float(h0));
        __nv_bfloat16 l1 = __float2bfloat16_rn(v.y - __bfloat162float(h1));
        __nv_bfloat16 l2 = __float2bfloat16_rn(v.z - __bfloat162float(h2));
        __nv_bfloat16 l3 = __float2bfloat16_rn(v.w - __bfloat162float(h3));
        uint32_t h01 = ((uint32_t)__bfloat16_as_ushort(h1) << 16) | __bfloat16_as_ushort(h0);
        uint32_t h23 = ((uint32_t)__bfloat16_as_ushort(h3) << 16) | __bfloat16_as_ushort(h2);
        uint32_t l01 = ((uint32_t)__bfloat16_as_ushort(l1) << 16) | __bfloat16_as_ushort(l0);
        uint32_t l23 = ((uint32_t)__bfloat16_as_ushort(l3) << 16) | __bfloat16_as_ushort(l2);
        uint32_t ro = (uint32_t)(r * ROWB + f4 * 8);
        sts64_2(st + T_AHI + ro, h01, h23);
        sts64_2(st + T_ALO + ro, l01, l23);
    }
}

__global__ __launch_bounds__(256, 2) void k_gemm1_mma(const float* __restrict__ x,
                                                      const float* __restrict__ b1) {
    extern __shared__ char smem[];
    uint32_t sb = smem_u32(smem);
    uint32_t sA0 = sb + SM_AF32;
    uint32_t stiles = sb + SM_TILES;
    int t = threadIdx.x, wid = t >> 5, lane = t & 31;
    int wm = wid >> 1, wn = wid & 1;           // 4 x 2 warp grid
    int bn = blockIdx.x, bm = blockIdx.y * 128;
    int r8 = lane & 7, mi = lane >> 3;

    float acc[2][8][4];
#pragma unroll
    for (int a = 0; a < 2; ++a)
#pragma unroll
        for (int b = 0; b < 8; ++b)
#pragma unroll
            for (int q = 0; q < 4; ++q) acc[a][b][q] = 0.f;

    fill_Af32(sA0, x, 0, bm, t);
    fill_B(stiles, 0, bn, t);
    cp_commit();

    for (int c = 0; c < 16; ++c) {
        cp_wait0();                      // chunk-c data resident (sA[c&1], B tiles stage c&1)
        __syncthreads();                 // visibility + prior compute's reads complete
        // issue next-chunk fills FIRST: they target the other sA buffer and the
        // other tile stage, both disjoint from everything chunk c touches.
        if (c < 15) {
            fill_Af32(sA0 + (uint32_t)((c + 1) & 1) * AF32_SZ, x, c + 1, bm, t);
            fill_B(stiles + (uint32_t)((c + 1) & 1) * STAGE, c + 1, bn, t);
            cp_commit();                 // overlaps with convert + mma below
        }
        uint32_t st = stiles + (uint32_t)(c & 1) * STAGE;
        convertA(sA0 + (uint32_t)(c & 1) * AF32_SZ, st, t);
        __syncthreads();                 // A tiles visible to all warps

#pragma unroll
        for (int ks = 0; ks < 2; ++ks) {
            uint32_t ahi[2][4], alo[2][4];
#pragma unroll
            for (int mt = 0; mt < 2; ++mt) {
                uint32_t ao = (uint32_t)((wm * 32 + mt * 16 + (mi & 1) * 8 + r8) * ROWB
                                         + (ks * 16 + (mi >> 1) * 8) * 2);
                ldsm4(ahi[mt], st + T_AHI + ao);
                ldsm4(alo[mt], st + T_ALO + ao);
            }
            uint32_t bhi[4][4], blo[4][4];
#pragma unroll
            for (int ng = 0; ng < 4; ++ng) {
                uint32_t bo = (uint32_t)((wn * 64 + ng * 16 + (mi >> 1) * 8 + r8) * ROWB
                                         + (ks * 16 + (mi & 1) * 8) * 2);
                ldsm4(bhi[ng], st + T_BHI + bo);
                ldsm4(blo[ng], st + T_BLO + bo);
            }
#pragma unroll
            for (int mt = 0; mt < 2; ++mt)
#pragma unroll
                for (int nt = 0; nt < 8; ++nt) {
                    const uint32_t* bh = &bhi[nt >> 1][(nt & 1) * 2];
                    const uint32_t* bl = &blo[nt >> 1][(nt & 1) * 2];
                    mma16816(acc[mt][nt], ahi[mt], bh);
                    mma16816(acc[mt][nt], ahi[mt], bl);
                    mma16816(acc[mt][nt], alo[mt], bh);
                }
        }
    }

    // epilogue: bias + relu
    int qr = lane >> 2, qc = (lane & 3) * 2;
#pragma unroll
    for (int nt = 0; nt < 8; ++nt) {
        int col = bn * 128 + wn * 64 + nt * 8 + qc;
        float bv0 = b1[col], bv1 = b1[col + 1];
#pragma unroll
        for (int mt = 0; mt < 2; ++mt) {
            int row0 = bm + wm * 32 + mt * 16 + qr;
            if (row0 < NN) {
                float2 v;
                v.x = fmaxf(acc[mt][nt][0] + bv0, 0.f);
                v.y = fmaxf(acc[mt][nt][1] + bv1, 0.f);
                *(float2*)(g_h1 + (size_t)row0 * HID + col) = v;
            }
            if (row0 + 8 < NN) {
                float2 v;
                v.x = fmaxf(acc[mt][nt][2] + bv0, 0.f);
                v.y = fmaxf(acc[mt][nt][3] + bv1, 0.f);
                *(float2*)(g_h1 + (size_t)(row0 + 8) * HID + col) = v;
            }
        }
    }
}

// ---------------- graph normalization + CSR build ----------------
__global__ void k_init() {
    int i = blockIdx.x * blockDim.x + threadIdx.x;
    if (i < NN) g_deg[i] = 1;
}
__global__ void k_count(const int* __restrict__ dst, int E) {
    int e = blockIdx.x * blockDim.x + threadIdx.x;
    if (e < E) atomicAdd(&g_deg[dst[e]], 1);
}
__global__ void k_dinv() {
    int i = blockIdx.x * blockDim.x + threadIdx.x;
    if (i < NN) g_dinv[i] = rsqrtf((float)g_deg[i]);
}
__global__ void k_scanA() {
    __shared__ int sh[256];
    int b = blockIdx.x, t = threadIdx.x;
    int base = b * 1024 + t * 4;
    int s = 0;
    if (base < NN) { int4 v = *(const int4*)(g_deg + base); s = v.x + v.y + v.z + v.w; }
    sh[t] = s; __syncthreads();
    for (int off = 128; off > 0; off >>= 1) {
        if (t < off) sh[t] += sh[t + off];
        __syncthreads();
    }
    if (t == 0) g_part[b] = sh[0];
}
__global__ void k_scanB(int nnz_total) {
    __shared__ int sh[128];
    int t = threadIdx.x;
    int v = (t < SCAN_NB) ? g_part[t] : 0;
    sh[t] = v; __syncthreads();
    for (int off = 1; off < 128; off <<= 1) {
        int u = (t >= off) ? sh[t - off] : 0;
        __syncthreads();
        sh[t] += u;
        __syncthreads();
    }
    g_part[t] = sh[t] - v;
    if (t == 0) g_rowptr[NN] = nnz_total;
}
__global__ void k_scanC() {
    __shared__ int sh[256];
    int b = blockIdx.x, t = threadIdx.x;
    int base = b * 1024 + t * 4;
    int4 v = make_int4(0, 0, 0, 0);
    if (base < NN) v = *(const int4*)(g_deg + base);
    int s1 = v.x, s2 = s1 + v.y, s3 = s2 + v.z, tot = s3 + v.w;
    sh[t] = tot; __syncthreads();
    for (int off = 1; off < 256; off <<= 1) {
        int u = (t >= off) ? sh[t - off] : 0;
        __syncthreads();
        sh[t] += u;
        __syncthreads();
    }
    int o = g_part[b] + sh[t] - tot;
    if (base < NN)
        *(int4*)(g_rowptr + base) = make_int4(o, o + s1, o + s2, o + s3);
}
__global__ void k_fill_self() {
    int i = blockIdx.x * blockDim.x + threadIdx.x;
    if (i >= NN) return;
    int p = g_rowptr[i];
    float di = g_dinv[i];
    g_csr[p] = make_int2(i, __float_as_int(di * di));
    g_cursor[i] = p + 1;
}
__global__ void k_fill_edges(const int* __restrict__ src, const int* __restrict__ dst, int E) {
    int e = blockIdx.x * blockDim.x + threadIdx.x;
    if (e >= E) return;
    int s = src[e], d = dst[e];
    int p = atomicAdd(&g_cursor[d], 1);
    g_csr[p] = make_int2(s, __float_as_int(g_dinv[s] * g_dinv[d]));
}

// ---------------- GEMM2: hh = h1 @ W2 + b2 ----------------
__global__ __launch_bounds__(256) void k_gemm2(const float* __restrict__ W2,
                                               const float* __restrict__ b2) {
    __shared__ float sW[HID * C];
    int t = threadIdx.x;
    for (int i = t; i < HID * C; i += 256) sW[i] = W2[i];
    __syncthreads();
    int row = blockIdx.x * 8 + (t >> 5);
    int lane = t & 31;
    if (row >= NN) return;
    const float4* h4 = (const float4*)(g_h1 + (size_t)row * HID);
    float a0 = 0.f, a1 = 0.f;
    int c1 = 32 + lane;
#pragma unroll 4
    for (int k4 = 0; k4 < HID / 4; k4++) {
        float4 h = h4[k4];
        int kb = k4 * 4;
        a0 = fmaf(h.x, sW[(kb + 0) * C + lane], a0);
        a0 = fmaf(h.y, sW[(kb + 1) * C + lane], a0);
        a0 = fmaf(h.z, sW[(kb + 2) * C + lane], a0);
        a0 = fmaf(h.w, sW[(kb + 3) * C + lane], a0);
        if (lane < 8) {
            a1 = fmaf(h.x, sW[(kb + 0) * C + c1], a1);
            a1 = fmaf(h.y, sW[(kb + 1) * C + c1], a1);
            a1 = fmaf(h.z, sW[(kb + 2) * C + c1], a1);
            a1 = fmaf(h.w, sW[(kb + 3) * C + c1], a1);
        }
    }
    float* o = g_hh + (size_t)row * C;
    o[lane] = a0 + b2[lane];
    if (lane < 8) o[c1] = a1 + b2[c1];
}

// ---------------- fused SpMM + L21 proximal (simple loop — best measured, R15) ----------------
__global__ __launch_bounds__(256) void k_amp(int it) {
    const float* __restrict__ xin = (it == 0) ? g_hh : ((it & 1) ? g_xa : g_xb);
    float* __restrict__ xout = (it & 1) ? g_xb : g_xa;
    int gid = blockIdx.x * blockDim.x + threadIdx.x;
    int i = gid >> 5, lane = gid & 31;
    if (i >= NN) return;
    int rs = g_rowptr[i], re = g_rowptr[i + 1];
    float a0 = 0.f, a1 = 0.f;
    for (int e = rs; e < re; ++e) {
        int2 cv = g_csr[e];
        float v = __int_as_float(cv.y);
        const float* xr = xin + (size_t)cv.x * C;
        a0 = fmaf(v, xr[lane], a0);
        if (lane < 8) a1 = fmaf(v, xr[32 + lane], a1);
    }
    float h0 = g_hh[(size_t)i * C + lane];
    float d0 = a0 - h0;
    float h1v = 0.f, d1 = 0.f;
    if (lane < 8) { h1v = g_hh[(size_t)i * C + 32 + lane]; d1 = a1 - h1v; }
    float p = d0 * d0 + d1 * d1;
#pragma unroll
    for (int off = 16; off > 0; off >>= 1) p += __shfl_xor_sync(0xffffffffu, p, off);
    float rn = sqrtf(p);
    float sc = 0.f;
    if (rn > 0.f) sc = fmaxf(rn - LAM, 0.f) / rn;
    xout[(size_t)i * C + lane] = h0 + sc * d0;
    if (lane < 8) xout[(size_t)i * C + 32 + lane] = h1v + sc * d1;
    if (lane == 0) g_score[i] = sc;
}

// ---------------- log_softmax + output assembly ----------------
__global__ __launch_bounds__(256) void k_out(float* __restrict__ out) {
    int gid = blockIdx.x * blockDim.x + threadIdx.x;
    int i = gid >> 5, lane = gid & 31;
    if (i >= NN) return;
    const float* xr = g_xb + (size_t)i * C;
    float v0 = xr[lane];
    float v1 = (lane < 8) ? xr[32 + lane] : 0.f;
    float m = (lane < 8) ? fmaxf(v0, v1) : v0;
#pragma unroll
    for (int off = 16; off > 0; off >>= 1) m = fmaxf(m, __shfl_xor_sync(0xffffffffu, m, off));
    float s = expf(v0 - m) + ((lane < 8) ? expf(v1 - m) : 0.f);
#pragma unroll
    for (int off = 16; off > 0; off >>= 1) s += __shfl_xor_sync(0xffffffffu, s, off);
    float l = logf(s);
    out[(size_t)i * C + lane] = v0 - m - l;
    if (lane < 8) out[(size_t)i * C + 32 + lane] = v1 - m - l;
    if (lane == 0) out[(size_t)NN * C + i] = g_score[i];
}

// ---------------- launch ----------------
extern "C" void kernel_launch(void* const* d_in, const int* in_sizes, int n_in,
                              void* d_out, int out_size) {
    const float* x   = (const float*)d_in[0];
    const float* W1  = (const float*)d_in[1];
    const float* b1  = (const float*)d_in[2];
    const float* W2  = (const float*)d_in[3];
    const float* b2  = (const float*)d_in[4];
    const int* esrc  = (const int*)d_in[5];
    const int* edst  = (const int*)d_in[6];
    int E = in_sizes[5];
    if (E > EE) E = EE;
    float* out = (float*)d_out;

    cudaFuncSetAttribute(k_gemm1_mma, cudaFuncAttributeMaxDynamicSharedMemorySize, SM_G1);

    // order keeps gemm1 at launch index 3 (= ncu capture slot)
    k_convW<<<(HID * KPAD + 255) / 256, 256>>>(W1);             // 0
    k_init<<<(NN + 255) / 256, 256>>>();                        // 1
    k_count<<<(E + 255) / 256, 256>>>(edst, E);                 // 2
    {
        dim3 g1(2, MPAD / 128);
        k_gemm1_mma<<<g1, 256, SM_G1>>>(x, b1);                 // 3  (ncu slot)
    }

    // graph normalization + CSR build
    k_dinv<<<(NN + 255) / 256, 256>>>();
    k_scanA<<<SCAN_NB, 256>>>();
    k_scanB<<<1, 128>>>(E + NN);
    k_scanC<<<SCAN_NB, 256>>>();
    k_fill_self<<<(NN + 255) / 256, 256>>>();
    k_fill_edges<<<(E + 255) / 256, 256>>>(esrc, edst, E);

    // MLP second layer
    k_gemm2<<<(NN + 7) / 8, 256>>>(W2, b2);

    // 10 AMP iterations (ping-pong)
    int warpBlocks = (NN * 32 + 255) / 256;
    for (int it = 0; it < 10; ++it)
        k_amp<<<warpBlocks, 256>>>(it);

    // log_softmax + score
    k_out<<<warpBlocks, 256>>>(out);
}